// round 6
// baseline (speedup 1.0000x reference)
#include <cuda_runtime.h>
#include <cuda_bf16.h>
#include <cstdint>

#define Bb 8
#define Cc 512
#define Ll 4096
#define Dd 64

// ---------------------------------------------------------------------------
// Scratch (device globals)
// ---------------------------------------------------------------------------
__device__ __nv_bfloat16 g_qa[(size_t)Bb * Ll * 128];   // [B,L,128] = [qhi|qlo]
__device__ __nv_bfloat16 g_kb[(size_t)Bb * Ll * 128];   // [B,L,128] = [khi|khi]
__device__ __nv_bfloat16 g_xT[(size_t)Bb * Ll * Cc];    // [B,L,C] bf16
__device__ __nv_bfloat16 g_wv[(size_t)Cc * Cc];         // [C,C] bf16
__device__ __nv_bfloat16 g_v [(size_t)Bb * Cc * Ll];    // [B,C,L] bf16
__device__ __nv_bfloat16 g_p [(size_t)Bb * Ll * Ll];    // [B,L,L] exp(energy) bf16
__device__ float g_spart[(size_t)Bb * 32 * Ll];         // [B,jtile,L] row-sum partials
__device__ float g_invs [(size_t)Bb * Ll];              // [B,L] 1/rowsum

// ---------------------------------------------------------------------------
// helpers
// ---------------------------------------------------------------------------
__device__ __forceinline__ uint32_t smem_u32(const void* p) {
    uint32_t a;
    asm("{ .reg .u64 t; cvta.to.shared.u64 t, %1; cvt.u32.u64 %0, t; }"
        : "=r"(a) : "l"(p));
    return a;
}
__device__ __forceinline__ void cp16u(uint32_t s, const void* g) {
    asm volatile("cp.async.cg.shared.global [%0], [%1], 16;" :: "r"(s), "l"(g));
}
__device__ __forceinline__ void ldsm_x4(uint32_t* r, uint32_t addr) {
    asm volatile("ldmatrix.sync.aligned.m8n8.x4.shared.b16 {%0,%1,%2,%3}, [%4];"
                 : "=r"(r[0]), "=r"(r[1]), "=r"(r[2]), "=r"(r[3]) : "r"(addr));
}
__device__ __forceinline__ void mma16816(float* d, const uint32_t* a, const uint32_t* b) {
    asm volatile(
        "mma.sync.aligned.m16n8k16.row.col.f32.bf16.bf16.f32 "
        "{%0,%1,%2,%3}, {%4,%5,%6,%7}, {%8,%9}, {%0,%1,%2,%3};"
        : "+f"(d[0]), "+f"(d[1]), "+f"(d[2]), "+f"(d[3])
        : "r"(a[0]), "r"(a[1]), "r"(a[2]), "r"(a[3]), "r"(b[0]), "r"(b[1]));
}

// dynamic smem: 3 stages x (A 16KB + B 16KB) = 96KB, s_part 1KB @98304
static constexpr int STAGE_BYTES = 32768;
static constexpr int SMEM_SZ = 3 * STAGE_BYTES + 1024;

// ---------------------------------------------------------------------------
// HMMA bf16 GEMM: D[m][n] = sum_k A[m][k]*B[n][k] (both K-major).
// CTA 128x128, 128 threads (4 warps, 2m x 2n), warptile 64x64, k-tile 64,
// XOR-swizzled smem, 3-stage cp.async pipeline, ONE __syncthreads per k-tile.
// EPI: 1 = +bias[m], store bf16
//      2 = (gamma*invS[n])*acc + X[m][n], store fp32
//      3 = exp(acc) -> bf16 store; per-CTA row sums -> spart
// ---------------------------------------------------------------------------
template <int EPI>
__global__ __launch_bounds__(128) void hgemm(
    const __nv_bfloat16* __restrict__ Aall,
    const __nv_bfloat16* __restrict__ Ball,
    void* __restrict__ Cout,
    int K, int ldC,
    long long sA, long long sB, long long sC,
    const float* __restrict__ bias,
    const float* __restrict__ gptr,
    const float* __restrict__ Xall, long long sX,
    float* __restrict__ spart,
    const float* __restrict__ invS)
{
    extern __shared__ __align__(1024) char sm[];
    const uint32_t smA = smem_u32(sm);                 // stage s: smA + s*32768
    const uint32_t smB = smA + 16384;
    float* s_part = (float*)(sm + 3 * STAGE_BYTES);

    const int t = threadIdx.x, lane = t & 31, wid = t >> 5;
    const int bz = blockIdx.z;
    const int m0 = blockIdx.y * 128, n0 = blockIdx.x * 128;
    const int wm = wid & 1, wn = wid >> 1;             // 2x2 warp grid

    const __nv_bfloat16* A = Aall + (size_t)bz * sA + (size_t)m0 * K;
    const __nv_bfloat16* B = Ball + (size_t)bz * sB + (size_t)n0 * K;

    // loader: thread t owns row t of both A and B tiles (8 x 16B chunks each)
    const int lswz = t & 7;
    const __nv_bfloat16* Ar = A + (size_t)t * K;
    const __nv_bfloat16* Br = B + (size_t)t * K;
    const uint32_t dA0 = smA + t * 128;
    const uint32_t dB0 = smB + t * 128;

    float acc[4][8][4];
#pragma unroll
    for (int i = 0; i < 4; i++)
#pragma unroll
        for (int j = 0; j < 8; j++)
#pragma unroll
            for (int q = 0; q < 4; q++) acc[i][j][q] = 0.f;

#define LOAD_TILE(stg, k0)                                                   \
    do {                                                                     \
        _Pragma("unroll")                                                    \
        for (int c = 0; c < 8; c++) {                                        \
            uint32_t ph = (uint32_t)((c ^ lswz) << 4);                       \
            cp16u(dA0 + (stg) * STAGE_BYTES + ph, Ar + (k0) + c * 8);        \
            cp16u(dB0 + (stg) * STAGE_BYTES + ph, Br + (k0) + c * 8);        \
        }                                                                    \
        asm volatile("cp.async.commit_group;");                              \
    } while (0)

    const int nk = K / 64;
    LOAD_TILE(0, 0);
    if (nk > 1) { LOAD_TILE(1, 64); }
    else        { asm volatile("cp.async.commit_group;"); }

    const int a_r = lane & 15;
    const int a_ch = lane >> 4;         // 0/1
    const int b_r = ((lane >> 4) << 3) + (lane & 7);
    const int b_ch = (lane >> 3) & 1;   // 0/1

    int buf = 0;
    for (int kt = 0; kt < nk; kt++) {
        asm volatile("cp.async.wait_group 1;");
        __syncthreads();

        const int nxt = kt + 2;
        if (nxt < nk) {
            const int slot = (buf + 2 >= 3) ? buf - 1 : buf + 2;
            LOAD_TILE(slot, nxt * 64);
        } else {
            asm volatile("cp.async.commit_group;");
        }

        const uint32_t bA = smA + buf * STAGE_BYTES;
        const uint32_t bB = smB + buf * STAGE_BYTES;
#pragma unroll
        for (int s = 0; s < 4; s++) {
            uint32_t af[4][4];
#pragma unroll
            for (int mt = 0; mt < 4; mt++) {
                int r = wm * 64 + mt * 16 + a_r;
                int c = s * 2 + a_ch;
                ldsm_x4(af[mt], bA + r * 128 + ((c ^ (r & 7)) << 4));
            }
            uint32_t bf_[4][4];
#pragma unroll
            for (int ng = 0; ng < 4; ng++) {
                int r = wn * 64 + ng * 16 + b_r;
                int c = s * 2 + b_ch;
                ldsm_x4(bf_[ng], bB + r * 128 + ((c ^ (r & 7)) << 4));
            }
#pragma unroll
            for (int mt = 0; mt < 4; mt++)
#pragma unroll
                for (int nt = 0; nt < 8; nt++)
                    mma16816(acc[mt][nt], af[mt], &bf_[nt >> 1][(nt & 1) * 2]);
        }
        buf = (buf + 1 == 3) ? 0 : buf + 1;
    }
#undef LOAD_TILE

    // ---------------- epilogue ----------------
    const int cr = lane >> 2;
    const int cc = (lane & 3) * 2;

    if (EPI == 1) {
        __nv_bfloat16* C = (__nv_bfloat16*)Cout + (size_t)bz * sC;
#pragma unroll
        for (int mt = 0; mt < 4; mt++) {
            float bv0 = bias[m0 + wm * 64 + mt * 16 + cr];
            float bv1 = bias[m0 + wm * 64 + mt * 16 + cr + 8];
#pragma unroll
            for (int nt = 0; nt < 8; nt++) {
                int col = n0 + wn * 64 + nt * 8 + cc;
#pragma unroll
                for (int h = 0; h < 2; h++) {
                    int row = m0 + wm * 64 + mt * 16 + cr + h * 8;
                    float bv = h ? bv1 : bv0;
                    __nv_bfloat162 o;
                    o.x = __float2bfloat16(acc[mt][nt][h * 2] + bv);
                    o.y = __float2bfloat16(acc[mt][nt][h * 2 + 1] + bv);
                    *(__nv_bfloat162*)(C + (size_t)row * ldC + col) = o;
                }
            }
        }
    } else if (EPI == 2) {
        const float g = gptr[0];
        const float* X = Xall + (size_t)bz * sX;
        const float* iS = invS + (size_t)bz * Ll;
        float* C = (float*)Cout + (size_t)bz * sC;
#pragma unroll
        for (int nt = 0; nt < 8; nt++) {
            int col = n0 + wn * 64 + nt * 8 + cc;
            float gi0 = g * iS[col];
            float gi1 = g * iS[col + 1];
#pragma unroll
            for (int mt = 0; mt < 4; mt++)
#pragma unroll
                for (int h = 0; h < 2; h++) {
                    int row = m0 + wm * 64 + mt * 16 + cr + h * 8;
                    float2 xv = *(const float2*)(X + (size_t)row * ldC + col);
                    float2 o;
                    o.x = fmaf(gi0, acc[mt][nt][h * 2], xv.x);
                    o.y = fmaf(gi1, acc[mt][nt][h * 2 + 1], xv.y);
                    *(float2*)(C + (size_t)row * ldC + col) = o;
                }
        }
    } else {
        // EPI 3: exp + bf16 store + row-sum partials
        __nv_bfloat16* C = (__nv_bfloat16*)Cout + (size_t)bz * sC;
        float rs[4][2];
#pragma unroll
        for (int mt = 0; mt < 4; mt++) { rs[mt][0] = 0.f; rs[mt][1] = 0.f; }
#pragma unroll
        for (int mt = 0; mt < 4; mt++)
#pragma unroll
            for (int nt = 0; nt < 8; nt++) {
                int col = n0 + wn * 64 + nt * 8 + cc;
#pragma unroll
                for (int h = 0; h < 2; h++) {
                    int row = m0 + wm * 64 + mt * 16 + cr + h * 8;
                    float e0 = __expf(acc[mt][nt][h * 2]);
                    float e1 = __expf(acc[mt][nt][h * 2 + 1]);
                    __nv_bfloat162 o;
                    o.x = __float2bfloat16(e0);
                    o.y = __float2bfloat16(e1);
                    *(__nv_bfloat162*)(C + (size_t)row * ldC + col) = o;
                    rs[mt][h] += e0 + e1;
                }
            }
#pragma unroll
        for (int mt = 0; mt < 4; mt++)
#pragma unroll
            for (int h = 0; h < 2; h++) {
                float v = rs[mt][h];
                v += __shfl_xor_sync(0xffffffffu, v, 1);
                v += __shfl_xor_sync(0xffffffffu, v, 2);
                rs[mt][h] = v;
            }
        __syncthreads();
        if ((lane & 3) == 0) {
#pragma unroll
            for (int mt = 0; mt < 4; mt++)
#pragma unroll
                for (int h = 0; h < 2; h++)
                    s_part[wn * 128 + wm * 64 + mt * 16 + cr + h * 8] = rs[mt][h];
        }
        __syncthreads();
        {
            size_t idx = ((size_t)bz * 32 + blockIdx.x) * Ll + m0 + t;
            spart[idx] = s_part[t] + s_part[128 + t];
        }
    }
}

// ---------------------------------------------------------------------------
// reduce partials -> 1/rowsum
// ---------------------------------------------------------------------------
__global__ __launch_bounds__(256) void reduce_s_kernel()
{
    int idx = blockIdx.x * 256 + threadIdx.x;     // 0 .. B*L-1
    int b = idx >> 12, m = idx & 4095;
    float s = 0.f;
#pragma unroll 8
    for (int nt = 0; nt < 32; nt++)
        s += g_spart[((size_t)b * 32 + nt) * Ll + m];
    g_invs[idx] = 1.0f / s;
}

// ---------------------------------------------------------------------------
// q/k projection -> bf16 layouts (fp32 math)
// q = [qhi|qlo] (exact split), k = [khi|khi] (single bf16, duplicated)
// ---------------------------------------------------------------------------
__global__ __launch_bounds__(256) void proj_qk_kernel(
    const float* __restrict__ x,
    const float* __restrict__ Wq, const float* __restrict__ bq,
    const float* __restrict__ Wk, const float* __restrict__ bk)
{
    const int b  = blockIdx.y;
    const int l0 = blockIdx.x * 64;

    __shared__ float xs[64][64];
    __shared__ float wqs[64][65];
    __shared__ float wks[64][65];

    const int t  = threadIdx.x;
    const int tx = t & 63;
    const int ty = t >> 6;

    float accq[16], acck[16];
#pragma unroll
    for (int i = 0; i < 16; i++) { accq[i] = 0.f; acck[i] = 0.f; }

    const float* xb = x + (size_t)b * Cc * Ll;
    const int row  = t >> 2;
    const int off0 = (t & 3) * 16;

    for (int cc = 0; cc < Cc; cc += 64) {
#pragma unroll
        for (int j = 0; j < 16; j += 4) {
            float4 v = *(const float4*)(xb + (size_t)(cc + row) * Ll + l0 + off0 + j);
            *(float4*)&xs[row][off0 + j] = v;
        }
#pragma unroll
        for (int j = 0; j < 16; j += 4) {
            float4 vq = *(const float4*)(Wq + row * Cc + cc + off0 + j);
            wqs[off0 + j + 0][row] = vq.x;
            wqs[off0 + j + 1][row] = vq.y;
            wqs[off0 + j + 2][row] = vq.z;
            wqs[off0 + j + 3][row] = vq.w;
            float4 vk = *(const float4*)(Wk + row * Cc + cc + off0 + j);
            wks[off0 + j + 0][row] = vk.x;
            wks[off0 + j + 1][row] = vk.y;
            wks[off0 + j + 2][row] = vk.z;
            wks[off0 + j + 3][row] = vk.w;
        }
        __syncthreads();
#pragma unroll 4
        for (int ci = 0; ci < 64; ci++) {
            float wq = wqs[ci][tx];
            float wk = wks[ci][tx];
#pragma unroll
            for (int i = 0; i < 16; i++) {
                float xv = xs[ci][ty * 16 + i];
                accq[i] = fmaf(wq, xv, accq[i]);
                acck[i] = fmaf(wk, xv, acck[i]);
            }
        }
        __syncthreads();
    }

    const float bqv = bq[tx];
    const float bkv = bk[tx];
#pragma unroll
    for (int i = 0; i < 16; i++) {
        int l = l0 + ty * 16 + i;
        size_t base = ((size_t)b * Ll + l) * 128;
        float qv = accq[i] + bqv;
        __nv_bfloat16 qh = __float2bfloat16(qv);
        __nv_bfloat16 ql = __float2bfloat16(qv - __bfloat162float(qh));
        g_qa[base + tx]      = qh;
        g_qa[base + 64 + tx] = ql;
        float kv = acck[i] + bkv;
        __nv_bfloat16 kh = __float2bfloat16(kv);
        g_kb[base + tx]      = kh;
        g_kb[base + 64 + tx] = kh;
    }
}

// ---------------------------------------------------------------------------
__global__ __launch_bounds__(256) void transpose_x_kernel(const float* __restrict__ x)
{
    __shared__ float tile[32][33];
    const int b  = blockIdx.z;
    const int c0 = blockIdx.y * 32;
    const int l0 = blockIdx.x * 32;
    const int tx = threadIdx.x, ty = threadIdx.y;

    const float* xb = x + ((size_t)b * Cc + c0) * Ll + l0;
#pragma unroll
    for (int r = 0; r < 4; r++)
        tile[ty + r * 8][tx] = xb[(size_t)(ty + r * 8) * Ll + tx];
    __syncthreads();

    __nv_bfloat16* o = g_xT + (size_t)b * Ll * Cc;
#pragma unroll
    for (int r = 0; r < 4; r++) {
        int l = l0 + ty + r * 8;
        o[(size_t)l * Cc + c0 + tx] = __float2bfloat16(tile[tx][ty + r * 8]);
    }
}

__global__ __launch_bounds__(256) void conv_wv_kernel(const float* __restrict__ Wv)
{
    int idx = blockIdx.x * 256 + threadIdx.x;
    g_wv[idx] = __float2bfloat16(Wv[idx]);
}

// ---------------------------------------------------------------------------
extern "C" void kernel_launch(void* const* d_in, const int* in_sizes, int n_in,
                              void* d_out, int out_size)
{
    const float* x     = (const float*)d_in[0];
    const float* Wq    = (const float*)d_in[1];
    const float* bq    = (const float*)d_in[2];
    const float* Wk    = (const float*)d_in[3];
    const float* bk    = (const float*)d_in[4];
    const float* Wv    = (const float*)d_in[5];
    const float* bv    = (const float*)d_in[6];
    const float* gamma = (const float*)d_in[7];
    float* out = (float*)d_out;

    __nv_bfloat16 *qa, *kb, *xT, *wv, *v, *p;
    float *spart, *invs;
    cudaGetSymbolAddress((void**)&qa, g_qa);
    cudaGetSymbolAddress((void**)&kb, g_kb);
    cudaGetSymbolAddress((void**)&xT, g_xT);
    cudaGetSymbolAddress((void**)&wv, g_wv);
    cudaGetSymbolAddress((void**)&v,  g_v);
    cudaGetSymbolAddress((void**)&p,  g_p);
    cudaGetSymbolAddress((void**)&spart, g_spart);
    cudaGetSymbolAddress((void**)&invs,  g_invs);

    cudaFuncSetAttribute(hgemm<1>, cudaFuncAttributeMaxDynamicSharedMemorySize, SMEM_SZ);
    cudaFuncSetAttribute(hgemm<2>, cudaFuncAttributeMaxDynamicSharedMemorySize, SMEM_SZ);
    cudaFuncSetAttribute(hgemm<3>, cudaFuncAttributeMaxDynamicSharedMemorySize, SMEM_SZ);

    // 1) prologue conversions
    proj_qk_kernel<<<dim3(Ll / 64, Bb), 256>>>(x, Wq, bq, Wk, bk);
    transpose_x_kernel<<<dim3(Ll / 32, Cc / 32, Bb), dim3(32, 8)>>>(x);
    conv_wv_kernel<<<(Cc * Cc) / 256, 256>>>(Wv);

    // 2) v = Wv @ x + bv  -> bf16 [C, L]
    hgemm<1><<<dim3(Ll / 128, Cc / 128, Bb), 128, SMEM_SZ>>>(
        wv, xT, v, Cc, Ll,
        0LL, (long long)Ll * Cc, (long long)Cc * Ll,
        bv, nullptr, nullptr, 0LL, nullptr, nullptr);

    // 3) p = exp(q @ k^T)  (K=128: qhi|qlo vs khi|khi) -> bf16 + row-sum partials
    hgemm<3><<<dim3(Ll / 128, Ll / 128, Bb), 128, SMEM_SZ>>>(
        qa, kb, p, 128, Ll,
        (long long)Ll * 128, (long long)Ll * 128, (long long)Ll * Ll,
        nullptr, nullptr, nullptr, 0LL, spart, nullptr);

    // 4) invS = 1 / rowsum
    reduce_s_kernel<<<(Bb * Ll) / 256, 256>>>();

    // 5) out = (gamma*invS[i]) * (v @ p^T) + x  -> fp32 [C, L]
    hgemm<2><<<dim3(Ll / 128, Cc / 128, Bb), 128, SMEM_SZ>>>(
        v, p, out, Ll, Ll,
        (long long)Cc * Ll, (long long)Ll * Ll, (long long)Cc * Ll,
        nullptr, gamma, x, (long long)Cc * Ll, nullptr, invs);
}

// round 7
// speedup vs baseline: 1.3004x; 1.3004x over previous
#include <cuda_runtime.h>
#include <cuda_bf16.h>
#include <cstdint>

#define Bb 8
#define Cc 512
#define Ll 4096
#define Dd 64

// ---------------------------------------------------------------------------
// Scratch (device globals)
// ---------------------------------------------------------------------------
__device__ __nv_bfloat16 g_qa[(size_t)Bb * Ll * 128];   // [B,L,128] = [qhi|qlo]
__device__ __nv_bfloat16 g_kb[(size_t)Bb * Ll * 128];   // [B,L,128] = [khi|khi]
__device__ __nv_bfloat16 g_xT[(size_t)Bb * Ll * Cc];    // [B,L,C] bf16
__device__ __nv_bfloat16 g_wv[(size_t)Cc * Cc];         // [C,C] bf16
__device__ __nv_bfloat16 g_v [(size_t)Bb * Cc * Ll];    // [B,C,L] bf16
__device__ __nv_bfloat16 g_p [(size_t)Bb * Ll * Ll];    // [B,L,L] exp(energy) bf16
__device__ float g_spart[(size_t)Bb * 32 * Ll];         // [B,jtile,L] row-sum partials
__device__ float g_invs [(size_t)Bb * Ll];              // [B,L] 1/rowsum

// ---------------------------------------------------------------------------
// helpers
// ---------------------------------------------------------------------------
__device__ __forceinline__ uint32_t smem_u32(const void* p) {
    uint32_t a;
    asm("{ .reg .u64 t; cvta.to.shared.u64 t, %1; cvt.u32.u64 %0, t; }"
        : "=r"(a) : "l"(p));
    return a;
}
__device__ __forceinline__ void cp16u(uint32_t s, const void* g) {
    asm volatile("cp.async.cg.shared.global [%0], [%1], 16;" :: "r"(s), "l"(g));
}
__device__ __forceinline__ void ldsm_x4(uint32_t* r, uint32_t addr) {
    asm volatile("ldmatrix.sync.aligned.m8n8.x4.shared.b16 {%0,%1,%2,%3}, [%4];"
                 : "=r"(r[0]), "=r"(r[1]), "=r"(r[2]), "=r"(r[3]) : "r"(addr));
}
__device__ __forceinline__ void mma16816(float* d, const uint32_t* a, const uint32_t* b) {
    asm volatile(
        "mma.sync.aligned.m16n8k16.row.col.f32.bf16.bf16.f32 "
        "{%0,%1,%2,%3}, {%4,%5,%6,%7}, {%8,%9}, {%0,%1,%2,%3};"
        : "+f"(d[0]), "+f"(d[1]), "+f"(d[2]), "+f"(d[3])
        : "r"(a[0]), "r"(a[1]), "r"(a[2]), "r"(a[3]), "r"(b[0]), "r"(b[1]));
}

// dynamic smem: 3 stages x (A 16KB + B 16KB) = 96KB, s_part 1KB @98304
static constexpr int STAGE_BYTES = 32768;
static constexpr int SMEM_SZ = 3 * STAGE_BYTES + 1024;

// ---------------------------------------------------------------------------
// HMMA bf16 GEMM: D[m][n] = sum_k A[m][k]*B[n][k] (both K-major).
// CTA 128x128, 256 threads (8 warps, 4m x 2n), warptile 32x64, k-tile 64,
// XOR-swizzled smem, 3-stage cp.async pipeline, ONE __syncthreads per k-tile,
// REGISTER FRAGMENT DOUBLE-BUFFERING across the 4 s-steps.
// EPI: 1 = +bias[m], store bf16
//      2 = (gamma*invS[n])*acc + X[m][n], store fp32
//      3 = exp(acc) -> bf16 store; per-CTA row sums -> spart
// ---------------------------------------------------------------------------
template <int EPI>
__global__ __launch_bounds__(256, 2) void hgemm(
    const __nv_bfloat16* __restrict__ Aall,
    const __nv_bfloat16* __restrict__ Ball,
    void* __restrict__ Cout,
    int K, int ldC,
    long long sA, long long sB, long long sC,
    const float* __restrict__ bias,
    const float* __restrict__ gptr,
    const float* __restrict__ Xall, long long sX,
    float* __restrict__ spart,
    const float* __restrict__ invS)
{
    extern __shared__ __align__(1024) char sm[];
    const uint32_t smA = smem_u32(sm);                 // stage s: smA + s*32768
    const uint32_t smB = smA + 16384;
    float* s_part = (float*)(sm + 3 * STAGE_BYTES);

    const int t = threadIdx.x, lane = t & 31, wid = t >> 5;
    const int bz = blockIdx.z;
    const int m0 = blockIdx.y * 128, n0 = blockIdx.x * 128;
    const int wm = wid & 3, wn = wid >> 2;

    const __nv_bfloat16* A = Aall + (size_t)bz * sA + (size_t)m0 * K;
    const __nv_bfloat16* B = Ball + (size_t)bz * sB + (size_t)n0 * K;

    // loader: thread t -> row t>>1, chunks (t&1)*4 .. +3 (16B each)
    const int lrow = t >> 1;
    const int lc0  = (t & 1) * 4;
    const int lswz = lrow & 7;
    const __nv_bfloat16* Ar = A + (size_t)lrow * K;
    const __nv_bfloat16* Br = B + (size_t)lrow * K;
    const uint32_t dA0 = smA + lrow * 128;
    const uint32_t dB0 = smB + lrow * 128;

    float acc[2][8][4];
#pragma unroll
    for (int i = 0; i < 2; i++)
#pragma unroll
        for (int j = 0; j < 8; j++)
#pragma unroll
            for (int q = 0; q < 4; q++) acc[i][j][q] = 0.f;

#define LOAD_TILE(stg, k0)                                                   \
    do {                                                                     \
        _Pragma("unroll")                                                    \
        for (int j = 0; j < 4; j++) {                                        \
            int c = lc0 + j;                                                 \
            uint32_t ph = (uint32_t)((c ^ lswz) << 4);                       \
            cp16u(dA0 + (stg) * STAGE_BYTES + ph, Ar + (k0) + c * 8);        \
            cp16u(dB0 + (stg) * STAGE_BYTES + ph, Br + (k0) + c * 8);        \
        }                                                                    \
        asm volatile("cp.async.commit_group;");                              \
    } while (0)

    const int nk = K / 64;
    LOAD_TILE(0, 0);
    if (nk > 1) { LOAD_TILE(1, 64); }
    else        { asm volatile("cp.async.commit_group;"); }

    const int a_r = lane & 15;
    const int a_ch = lane >> 4;         // 0/1
    const int b_r = ((lane >> 4) << 3) + (lane & 7);
    const int b_ch = (lane >> 3) & 1;   // 0/1

    int buf = 0;
    for (int kt = 0; kt < nk; kt++) {
        asm volatile("cp.async.wait_group 1;");
        __syncthreads();

        const int nxt = kt + 2;
        if (nxt < nk) {
            const int slot = (buf + 2 >= 3) ? buf - 1 : buf + 2;
            LOAD_TILE(slot, nxt * 64);
        } else {
            asm volatile("cp.async.commit_group;");
        }

        const uint32_t bA = smA + buf * STAGE_BYTES;
        const uint32_t bB = smB + buf * STAGE_BYTES;

        // register fragment ping-pong across s-steps
        uint32_t af[2][2][4];
        uint32_t bf_[2][4][4];

#define LOAD_FRAGS(pp, s)                                                    \
    do {                                                                     \
        _Pragma("unroll")                                                    \
        for (int mt = 0; mt < 2; mt++) {                                     \
            int r = wm * 32 + mt * 16 + a_r;                                 \
            int c = (s) * 2 + a_ch;                                          \
            ldsm_x4(af[pp][mt], bA + r * 128 + ((c ^ (r & 7)) << 4));        \
        }                                                                    \
        _Pragma("unroll")                                                    \
        for (int ng = 0; ng < 4; ng++) {                                     \
            int r = wn * 64 + ng * 16 + b_r;                                 \
            int c = (s) * 2 + b_ch;                                          \
            ldsm_x4(bf_[pp][ng], bB + r * 128 + ((c ^ (r & 7)) << 4));       \
        }                                                                    \
    } while (0)

        LOAD_FRAGS(0, 0);
#pragma unroll
        for (int s = 0; s < 4; s++) {
            if (s < 3) LOAD_FRAGS((s + 1) & 1, s + 1);
#pragma unroll
            for (int mt = 0; mt < 2; mt++)
#pragma unroll
                for (int nt = 0; nt < 8; nt++)
                    mma16816(acc[mt][nt], af[s & 1][mt],
                             &bf_[s & 1][nt >> 1][(nt & 1) * 2]);
        }
#undef LOAD_FRAGS
        buf = (buf + 1 == 3) ? 0 : buf + 1;
    }
#undef LOAD_TILE

    // ---------------- epilogue ----------------
    const int cr = lane >> 2;
    const int cc = (lane & 3) * 2;

    if (EPI == 1) {
        __nv_bfloat16* C = (__nv_bfloat16*)Cout + (size_t)bz * sC;
#pragma unroll
        for (int mt = 0; mt < 2; mt++) {
            float bv0 = bias[m0 + wm * 32 + mt * 16 + cr];
            float bv1 = bias[m0 + wm * 32 + mt * 16 + cr + 8];
#pragma unroll
            for (int nt = 0; nt < 8; nt++) {
                int col = n0 + wn * 64 + nt * 8 + cc;
#pragma unroll
                for (int h = 0; h < 2; h++) {
                    int row = m0 + wm * 32 + mt * 16 + cr + h * 8;
                    float bv = h ? bv1 : bv0;
                    __nv_bfloat162 o;
                    o.x = __float2bfloat16(acc[mt][nt][h * 2] + bv);
                    o.y = __float2bfloat16(acc[mt][nt][h * 2 + 1] + bv);
                    *(__nv_bfloat162*)(C + (size_t)row * ldC + col) = o;
                }
            }
        }
    } else if (EPI == 2) {
        const float g = gptr[0];
        const float* X = Xall + (size_t)bz * sX;
        const float* iS = invS + (size_t)bz * Ll;
        float* C = (float*)Cout + (size_t)bz * sC;
#pragma unroll
        for (int nt = 0; nt < 8; nt++) {
            int col = n0 + wn * 64 + nt * 8 + cc;
            float gi0 = g * iS[col];
            float gi1 = g * iS[col + 1];
#pragma unroll
            for (int mt = 0; mt < 2; mt++)
#pragma unroll
                for (int h = 0; h < 2; h++) {
                    int row = m0 + wm * 32 + mt * 16 + cr + h * 8;
                    float2 xv = *(const float2*)(X + (size_t)row * ldC + col);
                    float2 o;
                    o.x = fmaf(gi0, acc[mt][nt][h * 2], xv.x);
                    o.y = fmaf(gi1, acc[mt][nt][h * 2 + 1], xv.y);
                    *(float2*)(C + (size_t)row * ldC + col) = o;
                }
        }
    } else {
        // EPI 3: exp + bf16 store + row-sum partials
        __nv_bfloat16* C = (__nv_bfloat16*)Cout + (size_t)bz * sC;
        float rs[2][2] = {{0.f, 0.f}, {0.f, 0.f}};
#pragma unroll
        for (int mt = 0; mt < 2; mt++)
#pragma unroll
            for (int nt = 0; nt < 8; nt++) {
                int col = n0 + wn * 64 + nt * 8 + cc;
#pragma unroll
                for (int h = 0; h < 2; h++) {
                    int row = m0 + wm * 32 + mt * 16 + cr + h * 8;
                    float e0 = __expf(acc[mt][nt][h * 2]);
                    float e1 = __expf(acc[mt][nt][h * 2 + 1]);
                    __nv_bfloat162 o;
                    o.x = __float2bfloat16(e0);
                    o.y = __float2bfloat16(e1);
                    *(__nv_bfloat162*)(C + (size_t)row * ldC + col) = o;
                    rs[mt][h] += e0 + e1;
                }
            }
#pragma unroll
        for (int mt = 0; mt < 2; mt++)
#pragma unroll
            for (int h = 0; h < 2; h++) {
                float v = rs[mt][h];
                v += __shfl_xor_sync(0xffffffffu, v, 1);
                v += __shfl_xor_sync(0xffffffffu, v, 2);
                rs[mt][h] = v;
            }
        __syncthreads();
        if ((lane & 3) == 0) {
#pragma unroll
            for (int mt = 0; mt < 2; mt++)
#pragma unroll
                for (int h = 0; h < 2; h++)
                    s_part[wn * 128 + wm * 32 + mt * 16 + cr + h * 8] = rs[mt][h];
        }
        __syncthreads();
        if (t < 128) {
            size_t idx = ((size_t)bz * 32 + blockIdx.x) * Ll + m0 + t;
            spart[idx] = s_part[t] + s_part[128 + t];
        }
    }
}

// ---------------------------------------------------------------------------
// reduce partials -> 1/rowsum
// ---------------------------------------------------------------------------
__global__ __launch_bounds__(256) void reduce_s_kernel()
{
    int idx = blockIdx.x * 256 + threadIdx.x;     // 0 .. B*L-1
    int b = idx >> 12, m = idx & 4095;
    float s = 0.f;
#pragma unroll 8
    for (int nt = 0; nt < 32; nt++)
        s += g_spart[((size_t)b * 32 + nt) * Ll + m];
    g_invs[idx] = 1.0f / s;
}

// ---------------------------------------------------------------------------
// q/k projection -> bf16 layouts (fp32 math)
// q = [qhi|qlo] (exact split), k = [khi|khi] (single bf16, duplicated)
// ---------------------------------------------------------------------------
__global__ __launch_bounds__(256) void proj_qk_kernel(
    const float* __restrict__ x,
    const float* __restrict__ Wq, const float* __restrict__ bq,
    const float* __restrict__ Wk, const float* __restrict__ bk)
{
    const int b  = blockIdx.y;
    const int l0 = blockIdx.x * 64;

    __shared__ float xs[64][64];
    __shared__ float wqs[64][65];
    __shared__ float wks[64][65];

    const int t  = threadIdx.x;
    const int tx = t & 63;
    const int ty = t >> 6;

    float accq[16], acck[16];
#pragma unroll
    for (int i = 0; i < 16; i++) { accq[i] = 0.f; acck[i] = 0.f; }

    const float* xb = x + (size_t)b * Cc * Ll;
    const int row  = t >> 2;
    const int off0 = (t & 3) * 16;

    for (int cc = 0; cc < Cc; cc += 64) {
#pragma unroll
        for (int j = 0; j < 16; j += 4) {
            float4 v = *(const float4*)(xb + (size_t)(cc + row) * Ll + l0 + off0 + j);
            *(float4*)&xs[row][off0 + j] = v;
        }
#pragma unroll
        for (int j = 0; j < 16; j += 4) {
            float4 vq = *(const float4*)(Wq + row * Cc + cc + off0 + j);
            wqs[off0 + j + 0][row] = vq.x;
            wqs[off0 + j + 1][row] = vq.y;
            wqs[off0 + j + 2][row] = vq.z;
            wqs[off0 + j + 3][row] = vq.w;
            float4 vk = *(const float4*)(Wk + row * Cc + cc + off0 + j);
            wks[off0 + j + 0][row] = vk.x;
            wks[off0 + j + 1][row] = vk.y;
            wks[off0 + j + 2][row] = vk.z;
            wks[off0 + j + 3][row] = vk.w;
        }
        __syncthreads();
#pragma unroll 4
        for (int ci = 0; ci < 64; ci++) {
            float wq = wqs[ci][tx];
            float wk = wks[ci][tx];
#pragma unroll
            for (int i = 0; i < 16; i++) {
                float xv = xs[ci][ty * 16 + i];
                accq[i] = fmaf(wq, xv, accq[i]);
                acck[i] = fmaf(wk, xv, acck[i]);
            }
        }
        __syncthreads();
    }

    const float bqv = bq[tx];
    const float bkv = bk[tx];
#pragma unroll
    for (int i = 0; i < 16; i++) {
        int l = l0 + ty * 16 + i;
        size_t base = ((size_t)b * Ll + l) * 128;
        float qv = accq[i] + bqv;
        __nv_bfloat16 qh = __float2bfloat16(qv);
        __nv_bfloat16 ql = __float2bfloat16(qv - __bfloat162float(qh));
        g_qa[base + tx]      = qh;
        g_qa[base + 64 + tx] = ql;
        float kv = acck[i] + bkv;
        __nv_bfloat16 kh = __float2bfloat16(kv);
        g_kb[base + tx]      = kh;
        g_kb[base + 64 + tx] = kh;
    }
}

// ---------------------------------------------------------------------------
__global__ __launch_bounds__(256) void transpose_x_kernel(const float* __restrict__ x)
{
    __shared__ float tile[32][33];
    const int b  = blockIdx.z;
    const int c0 = blockIdx.y * 32;
    const int l0 = blockIdx.x * 32;
    const int tx = threadIdx.x, ty = threadIdx.y;

    const float* xb = x + ((size_t)b * Cc + c0) * Ll + l0;
#pragma unroll
    for (int r = 0; r < 4; r++)
        tile[ty + r * 8][tx] = xb[(size_t)(ty + r * 8) * Ll + tx];
    __syncthreads();

    __nv_bfloat16* o = g_xT + (size_t)b * Ll * Cc;
#pragma unroll
    for (int r = 0; r < 4; r++) {
        int l = l0 + ty + r * 8;
        o[(size_t)l * Cc + c0 + tx] = __float2bfloat16(tile[tx][ty + r * 8]);
    }
}

__global__ __launch_bounds__(256) void conv_wv_kernel(const float* __restrict__ Wv)
{
    int idx = blockIdx.x * 256 + threadIdx.x;
    g_wv[idx] = __float2bfloat16(Wv[idx]);
}

// ---------------------------------------------------------------------------
extern "C" void kernel_launch(void* const* d_in, const int* in_sizes, int n_in,
                              void* d_out, int out_size)
{
    const float* x     = (const float*)d_in[0];
    const float* Wq    = (const float*)d_in[1];
    const float* bq    = (const float*)d_in[2];
    const float* Wk    = (const float*)d_in[3];
    const float* bk    = (const float*)d_in[4];
    const float* Wv    = (const float*)d_in[5];
    const float* bv    = (const float*)d_in[6];
    const float* gamma = (const float*)d_in[7];
    float* out = (float*)d_out;

    __nv_bfloat16 *qa, *kb, *xT, *wv, *v, *p;
    float *spart, *invs;
    cudaGetSymbolAddress((void**)&qa, g_qa);
    cudaGetSymbolAddress((void**)&kb, g_kb);
    cudaGetSymbolAddress((void**)&xT, g_xT);
    cudaGetSymbolAddress((void**)&wv, g_wv);
    cudaGetSymbolAddress((void**)&v,  g_v);
    cudaGetSymbolAddress((void**)&p,  g_p);
    cudaGetSymbolAddress((void**)&spart, g_spart);
    cudaGetSymbolAddress((void**)&invs,  g_invs);

    cudaFuncSetAttribute(hgemm<1>, cudaFuncAttributeMaxDynamicSharedMemorySize, SMEM_SZ);
    cudaFuncSetAttribute(hgemm<2>, cudaFuncAttributeMaxDynamicSharedMemorySize, SMEM_SZ);
    cudaFuncSetAttribute(hgemm<3>, cudaFuncAttributeMaxDynamicSharedMemorySize, SMEM_SZ);

    // 1) prologue conversions
    proj_qk_kernel<<<dim3(Ll / 64, Bb), 256>>>(x, Wq, bq, Wk, bk);
    transpose_x_kernel<<<dim3(Ll / 32, Cc / 32, Bb), dim3(32, 8)>>>(x);
    conv_wv_kernel<<<(Cc * Cc) / 256, 256>>>(Wv);

    // 2) v = Wv @ x + bv  -> bf16 [C, L]
    hgemm<1><<<dim3(Ll / 128, Cc / 128, Bb), 256, SMEM_SZ>>>(
        wv, xT, v, Cc, Ll,
        0LL, (long long)Ll * Cc, (long long)Cc * Ll,
        bv, nullptr, nullptr, 0LL, nullptr, nullptr);

    // 3) p = exp(q @ k^T)  (K=128: qhi|qlo vs khi|khi) -> bf16 + row-sum partials
    hgemm<3><<<dim3(Ll / 128, Ll / 128, Bb), 256, SMEM_SZ>>>(
        qa, kb, p, 128, Ll,
        (long long)Ll * 128, (long long)Ll * 128, (long long)Ll * Ll,
        nullptr, nullptr, nullptr, 0LL, spart, nullptr);

    // 4) invS = 1 / rowsum
    reduce_s_kernel<<<(Bb * Ll) / 256, 256>>>();

    // 5) out = (gamma*invS[i]) * (v @ p^T) + x  -> fp32 [C, L]
    hgemm<2><<<dim3(Ll / 128, Cc / 128, Bb), 256, SMEM_SZ>>>(
        v, p, out, Ll, Ll,
        (long long)Cc * Ll, (long long)Ll * Ll, (long long)Cc * Ll,
        nullptr, gamma, x, (long long)Cc * Ll, nullptr, invs);
}

// round 8
// speedup vs baseline: 1.3666x; 1.0509x over previous
#include <cuda_runtime.h>
#include <cuda_bf16.h>
#include <cuda_fp8.h>
#include <cstdint>

#define Bb 8
#define Cc 512
#define Ll 4096
#define Dd 64

// p is stored as e4m3 scaled by 2^-6; epilogue multiplies back by 64.
#define PSCALE (1.0f / 64.0f)

// ---------------------------------------------------------------------------
// Scratch (device globals)
// ---------------------------------------------------------------------------
__device__ __nv_bfloat16 g_qa[(size_t)Bb * Ll * Dd];    // [B,L,64] q bf16
__device__ __nv_bfloat16 g_kb[(size_t)Bb * Ll * Dd];    // [B,L,64] k bf16
__device__ __nv_bfloat16 g_xT[(size_t)Bb * Ll * Cc];    // [B,L,C] bf16
__device__ __nv_bfloat16 g_wv[(size_t)Cc * Cc];         // [C,C] bf16
__device__ unsigned char g_v [(size_t)Bb * Cc * Ll];    // [B,C,L] e4m3
__device__ unsigned char g_p [(size_t)Bb * Ll * Ll];    // [B,L,L] e4m3 exp(e)*2^-6
__device__ float g_spart[(size_t)Bb * 32 * Ll];         // [B,jtile,L] row-sum partials
__device__ float g_invs [(size_t)Bb * Ll];              // [B,L] 1/rowsum

// ---------------------------------------------------------------------------
// helpers
// ---------------------------------------------------------------------------
__device__ __forceinline__ uint32_t smem_u32(const void* p) {
    uint32_t a;
    asm("{ .reg .u64 t; cvta.to.shared.u64 t, %1; cvt.u32.u64 %0, t; }"
        : "=r"(a) : "l"(p));
    return a;
}
__device__ __forceinline__ void cp16u(uint32_t s, const void* g) {
    asm volatile("cp.async.cg.shared.global [%0], [%1], 16;" :: "r"(s), "l"(g));
}
__device__ __forceinline__ void ldsm_x4(uint32_t* r, uint32_t addr) {
    asm volatile("ldmatrix.sync.aligned.m8n8.x4.shared.b16 {%0,%1,%2,%3}, [%4];"
                 : "=r"(r[0]), "=r"(r[1]), "=r"(r[2]), "=r"(r[3]) : "r"(addr));
}
__device__ __forceinline__ void mma16816(float* d, const uint32_t* a, const uint32_t* b) {
    asm volatile(
        "mma.sync.aligned.m16n8k16.row.col.f32.bf16.bf16.f32 "
        "{%0,%1,%2,%3}, {%4,%5,%6,%7}, {%8,%9}, {%0,%1,%2,%3};"
        : "+f"(d[0]), "+f"(d[1]), "+f"(d[2]), "+f"(d[3])
        : "r"(a[0]), "r"(a[1]), "r"(a[2]), "r"(a[3]), "r"(b[0]), "r"(b[1]));
}
__device__ __forceinline__ void mma16832f8(float* d, const uint32_t* a,
                                           uint32_t b0, uint32_t b1) {
    asm volatile(
        "mma.sync.aligned.m16n8k32.row.col.f32.e4m3.e4m3.f32 "
        "{%0,%1,%2,%3}, {%4,%5,%6,%7}, {%8,%9}, {%0,%1,%2,%3};"
        : "+f"(d[0]), "+f"(d[1]), "+f"(d[2]), "+f"(d[3])
        : "r"(a[0]), "r"(a[1]), "r"(a[2]), "r"(a[3]), "r"(b0), "r"(b1));
}
__device__ __forceinline__ unsigned short f2_fp8x2(float a, float b) {
    float2 f; f.x = a; f.y = b;
    return (unsigned short)__nv_cvt_float2_to_fp8x2(f, __NV_SATFINITE, __NV_E4M3);
}

// dynamic smem: 3 stages x (A 16KB + B 16KB) = 96KB, s_part 1KB @98304
static constexpr int STAGE_BYTES = 32768;
static constexpr int SMEM_SZ = 3 * STAGE_BYTES + 1024;

// ---------------------------------------------------------------------------
// bf16 HMMA GEMM: D[m][n] = sum_k A[m][k]*B[n][k] (both K-major).
// CTA 128x128, 256 thr (8 warps, 4m x 2n), warptile 32x64, k-tile 64 bf16,
// 3-stage cp.async, one sync per k-tile, frag ping-pong.
// EPI 1: +bias[m], store e4m3
// EPI 3: exp(acc)*2^-6 -> e4m3 store; per-CTA row sums (unscaled) -> spart
// ---------------------------------------------------------------------------
template <int EPI>
__global__ __launch_bounds__(256, 2) void hgemm(
    const __nv_bfloat16* __restrict__ Aall,
    const __nv_bfloat16* __restrict__ Ball,
    unsigned char* __restrict__ Cout,
    int K, int ldC,
    long long sA, long long sB, long long sC,
    const float* __restrict__ bias,
    float* __restrict__ spart)
{
    extern __shared__ __align__(1024) char sm[];
    const uint32_t smA = smem_u32(sm);
    const uint32_t smB = smA + 16384;
    float* s_part = (float*)(sm + 3 * STAGE_BYTES);

    const int t = threadIdx.x, lane = t & 31, wid = t >> 5;
    const int bz = blockIdx.z;
    const int m0 = blockIdx.y * 128, n0 = blockIdx.x * 128;
    const int wm = wid & 3, wn = wid >> 2;

    const __nv_bfloat16* A = Aall + (size_t)bz * sA + (size_t)m0 * K;
    const __nv_bfloat16* B = Ball + (size_t)bz * sB + (size_t)n0 * K;

    const int lrow = t >> 1;
    const int lc0  = (t & 1) * 4;
    const int lswz = lrow & 7;
    const __nv_bfloat16* Ar = A + (size_t)lrow * K;
    const __nv_bfloat16* Br = B + (size_t)lrow * K;
    const uint32_t dA0 = smA + lrow * 128;
    const uint32_t dB0 = smB + lrow * 128;

    float acc[2][8][4];
#pragma unroll
    for (int i = 0; i < 2; i++)
#pragma unroll
        for (int j = 0; j < 8; j++)
#pragma unroll
            for (int q = 0; q < 4; q++) acc[i][j][q] = 0.f;

#define LOAD_TILE(stg, k0)                                                   \
    do {                                                                     \
        _Pragma("unroll")                                                    \
        for (int j = 0; j < 4; j++) {                                        \
            int c = lc0 + j;                                                 \
            uint32_t ph = (uint32_t)((c ^ lswz) << 4);                       \
            cp16u(dA0 + (stg) * STAGE_BYTES + ph, Ar + (k0) + c * 8);        \
            cp16u(dB0 + (stg) * STAGE_BYTES + ph, Br + (k0) + c * 8);        \
        }                                                                    \
        asm volatile("cp.async.commit_group;");                              \
    } while (0)

    const int nk = K / 64;
    LOAD_TILE(0, 0);
    if (nk > 1) LOAD_TILE(1, 64);

    const int a_r = lane & 15;
    const int a_ch = lane >> 4;
    const int b_r = ((lane >> 4) << 3) + (lane & 7);
    const int b_ch = (lane >> 3) & 1;

    int buf = 0;
    for (int kt = 0; kt < nk; kt++) {
        if (kt + 1 < nk) asm volatile("cp.async.wait_group 1;");
        else             asm volatile("cp.async.wait_group 0;");
        __syncthreads();

        if (kt + 2 < nk) {
            const int slot = (buf + 2 >= 3) ? buf - 1 : buf + 2;
            LOAD_TILE(slot, (kt + 2) * 64);
        }

        const uint32_t bA = smA + buf * STAGE_BYTES;
        const uint32_t bB = smB + buf * STAGE_BYTES;

        uint32_t af[2][2][4];
        uint32_t bf_[2][4][4];

#define LOAD_FRAGS(pp, s)                                                    \
    do {                                                                     \
        _Pragma("unroll")                                                    \
        for (int mt = 0; mt < 2; mt++) {                                     \
            int r = wm * 32 + mt * 16 + a_r;                                 \
            int c = (s) * 2 + a_ch;                                          \
            ldsm_x4(af[pp][mt], bA + r * 128 + ((c ^ (r & 7)) << 4));        \
        }                                                                    \
        _Pragma("unroll")                                                    \
        for (int ng = 0; ng < 4; ng++) {                                     \
            int r = wn * 64 + ng * 16 + b_r;                                 \
            int c = (s) * 2 + b_ch;                                          \
            ldsm_x4(bf_[pp][ng], bB + r * 128 + ((c ^ (r & 7)) << 4));       \
        }                                                                    \
    } while (0)

        LOAD_FRAGS(0, 0);
#pragma unroll
        for (int s = 0; s < 4; s++) {
            if (s < 3) LOAD_FRAGS((s + 1) & 1, s + 1);
#pragma unroll
            for (int mt = 0; mt < 2; mt++)
#pragma unroll
                for (int nt = 0; nt < 8; nt++)
                    mma16816(acc[mt][nt], af[s & 1][mt],
                             &bf_[s & 1][nt >> 1][(nt & 1) * 2]);
        }
#undef LOAD_FRAGS
        buf = (buf + 1 == 3) ? 0 : buf + 1;
    }
#undef LOAD_TILE

    // ---------------- epilogue ----------------
    const int cr = lane >> 2;
    const int cc = (lane & 3) * 2;

    if (EPI == 1) {
        unsigned char* C = Cout + (size_t)bz * sC;
#pragma unroll
        for (int mt = 0; mt < 2; mt++) {
            float bv0 = bias[m0 + wm * 32 + mt * 16 + cr];
            float bv1 = bias[m0 + wm * 32 + mt * 16 + cr + 8];
#pragma unroll
            for (int nt = 0; nt < 8; nt++) {
                int col = n0 + wn * 64 + nt * 8 + cc;
#pragma unroll
                for (int h = 0; h < 2; h++) {
                    int row = m0 + wm * 32 + mt * 16 + cr + h * 8;
                    float bv = h ? bv1 : bv0;
                    *(unsigned short*)(C + (size_t)row * ldC + col) =
                        f2_fp8x2(acc[mt][nt][h * 2] + bv, acc[mt][nt][h * 2 + 1] + bv);
                }
            }
        }
    } else {
        // EPI 3: exp*2^-6 -> e4m3 store + row-sum partials (unscaled)
        unsigned char* C = Cout + (size_t)bz * sC;
        float rs[2][2] = {{0.f, 0.f}, {0.f, 0.f}};
#pragma unroll
        for (int mt = 0; mt < 2; mt++)
#pragma unroll
            for (int nt = 0; nt < 8; nt++) {
                int col = n0 + wn * 64 + nt * 8 + cc;
#pragma unroll
                for (int h = 0; h < 2; h++) {
                    int row = m0 + wm * 32 + mt * 16 + cr + h * 8;
                    float e0 = __expf(acc[mt][nt][h * 2]);
                    float e1 = __expf(acc[mt][nt][h * 2 + 1]);
                    *(unsigned short*)(C + (size_t)row * ldC + col) =
                        f2_fp8x2(e0 * PSCALE, e1 * PSCALE);
                    rs[mt][h] += e0 + e1;
                }
            }
#pragma unroll
        for (int mt = 0; mt < 2; mt++)
#pragma unroll
            for (int h = 0; h < 2; h++) {
                float v = rs[mt][h];
                v += __shfl_xor_sync(0xffffffffu, v, 1);
                v += __shfl_xor_sync(0xffffffffu, v, 2);
                rs[mt][h] = v;
            }
        __syncthreads();
        if ((lane & 3) == 0) {
#pragma unroll
            for (int mt = 0; mt < 2; mt++)
#pragma unroll
                for (int h = 0; h < 2; h++)
                    s_part[wn * 128 + wm * 32 + mt * 16 + cr + h * 8] = rs[mt][h];
        }
        __syncthreads();
        if (t < 128) {
            size_t idx = ((size_t)bz * 32 + blockIdx.x) * Ll + m0 + t;
            spart[idx] = s_part[t] + s_part[128 + t];
        }
    }
}

// ---------------------------------------------------------------------------
// FP8 e4m3 GEMM (out): D[m][n] = sum_k A[m][k]*B[n][k], A/B K-major e4m3.
// CTA 128x128, k-tile 128 (bytes), same pipeline/warptile as hgemm.
// Epilogue: C = (gamma*invS[n]*64)*acc + X[m][n], fp32.
// ---------------------------------------------------------------------------
__global__ __launch_bounds__(256, 2) void fgemm(
    const unsigned char* __restrict__ Aall,
    const unsigned char* __restrict__ Ball,
    float* __restrict__ Cout,
    int K, int ldC,
    long long sA, long long sB, long long sC,
    const float* __restrict__ gptr,
    const float* __restrict__ Xall, long long sX,
    const float* __restrict__ invS)
{
    extern __shared__ __align__(1024) char sm[];
    const uint32_t smA = smem_u32(sm);
    const uint32_t smB = smA + 16384;

    const int t = threadIdx.x, lane = t & 31, wid = t >> 5;
    const int bz = blockIdx.z;
    const int m0 = blockIdx.y * 128, n0 = blockIdx.x * 128;
    const int wm = wid & 3, wn = wid >> 2;

    const unsigned char* A = Aall + (size_t)bz * sA + (size_t)m0 * K;
    const unsigned char* B = Ball + (size_t)bz * sB + (size_t)n0 * K;

    const int lrow = t >> 1;
    const int lc0  = (t & 1) * 4;
    const int lswz = lrow & 7;
    const unsigned char* Ar = A + (size_t)lrow * K;
    const unsigned char* Br = B + (size_t)lrow * K;
    const uint32_t dA0 = smA + lrow * 128;
    const uint32_t dB0 = smB + lrow * 128;

    float acc[2][8][4];
#pragma unroll
    for (int i = 0; i < 2; i++)
#pragma unroll
        for (int j = 0; j < 8; j++)
#pragma unroll
            for (int q = 0; q < 4; q++) acc[i][j][q] = 0.f;

#define LOAD_TILE8(stg, k0)                                                  \
    do {                                                                     \
        _Pragma("unroll")                                                    \
        for (int j = 0; j < 4; j++) {                                        \
            int c = lc0 + j;                                                 \
            uint32_t ph = (uint32_t)((c ^ lswz) << 4);                       \
            cp16u(dA0 + (stg) * STAGE_BYTES + ph, Ar + (k0) + c * 16);       \
            cp16u(dB0 + (stg) * STAGE_BYTES + ph, Br + (k0) + c * 16);       \
        }                                                                    \
        asm volatile("cp.async.commit_group;");                              \
    } while (0)

    const int nk = K / 128;            // k-tile = 128 fp8 bytes
    LOAD_TILE8(0, 0);
    if (nk > 1) LOAD_TILE8(1, 128);

    const int a_r = lane & 15;
    const int a_ch = lane >> 4;
    const int b_r = ((lane >> 4) << 3) + (lane & 7);
    const int b_ch = (lane >> 3) & 1;

    int buf = 0;
    for (int kt = 0; kt < nk; kt++) {
        if (kt + 1 < nk) asm volatile("cp.async.wait_group 1;");
        else             asm volatile("cp.async.wait_group 0;");
        __syncthreads();

        if (kt + 2 < nk) {
            const int slot = (buf + 2 >= 3) ? buf - 1 : buf + 2;
            LOAD_TILE8(slot, (kt + 2) * 128);
        }

        const uint32_t bA = smA + buf * STAGE_BYTES;
        const uint32_t bB = smB + buf * STAGE_BYTES;

        uint32_t af[2][2][4];
        uint32_t bf_[2][4][4];

#define LOAD_FRAGS8(pp, s)                                                   \
    do {                                                                     \
        _Pragma("unroll")                                                    \
        for (int mt = 0; mt < 2; mt++) {                                     \
            int r = wm * 32 + mt * 16 + a_r;                                 \
            int c = (s) * 2 + a_ch;                                          \
            ldsm_x4(af[pp][mt], bA + r * 128 + ((c ^ (r & 7)) << 4));        \
        }                                                                    \
        _Pragma("unroll")                                                    \
        for (int ng = 0; ng < 4; ng++) {                                     \
            int r = wn * 64 + ng * 16 + b_r;                                 \
            int c = (s) * 2 + b_ch;                                          \
            ldsm_x4(bf_[pp][ng], bB + r * 128 + ((c ^ (r & 7)) << 4));       \
        }                                                                    \
    } while (0)

        LOAD_FRAGS8(0, 0);
#pragma unroll
        for (int s = 0; s < 4; s++) {        // 4 s-steps x k32 = 128
            if (s < 3) LOAD_FRAGS8((s + 1) & 1, s + 1);
#pragma unroll
            for (int mt = 0; mt < 2; mt++)
#pragma unroll
                for (int nt = 0; nt < 8; nt++)
                    mma16832f8(acc[mt][nt], af[s & 1][mt],
                               bf_[s & 1][nt >> 1][(nt & 1) * 2],
                               bf_[s & 1][nt >> 1][(nt & 1) * 2 + 1]);
        }
#undef LOAD_FRAGS8
        buf = (buf + 1 == 3) ? 0 : buf + 1;
    }
#undef LOAD_TILE8

    // ---------------- epilogue: gamma*invS*64*acc + X ----------------
    const int cr = lane >> 2;
    const int cc = (lane & 3) * 2;
    const float g = gptr[0] * 64.0f;   // undo PSCALE
    const float* X = Xall + (size_t)bz * sX;
    const float* iS = invS + (size_t)bz * Ll;
    float* C = Cout + (size_t)bz * sC;
#pragma unroll
    for (int nt = 0; nt < 8; nt++) {
        int col = n0 + wn * 64 + nt * 8 + cc;
        float gi0 = g * iS[col];
        float gi1 = g * iS[col + 1];
#pragma unroll
        for (int mt = 0; mt < 2; mt++)
#pragma unroll
            for (int h = 0; h < 2; h++) {
                int row = m0 + wm * 32 + mt * 16 + cr + h * 8;
                float2 xv = *(const float2*)(X + (size_t)row * ldC + col);
                float2 o;
                o.x = fmaf(gi0, acc[mt][nt][h * 2], xv.x);
                o.y = fmaf(gi1, acc[mt][nt][h * 2 + 1], xv.y);
                *(float2*)(C + (size_t)row * ldC + col) = o;
            }
    }
}

// ---------------------------------------------------------------------------
// reduce partials -> 1/rowsum
// ---------------------------------------------------------------------------
__global__ __launch_bounds__(256) void reduce_s_kernel()
{
    int idx = blockIdx.x * 256 + threadIdx.x;
    int b = idx >> 12, m = idx & 4095;
    float s = 0.f;
#pragma unroll 8
    for (int nt = 0; nt < 32; nt++)
        s += g_spart[((size_t)b * 32 + nt) * Ll + m];
    g_invs[idx] = 1.0f / s;
}

// ---------------------------------------------------------------------------
// q/k projection -> bf16 (fp32 math), K=64 each
// ---------------------------------------------------------------------------
__global__ __launch_bounds__(256) void proj_qk_kernel(
    const float* __restrict__ x,
    const float* __restrict__ Wq, const float* __restrict__ bq,
    const float* __restrict__ Wk, const float* __restrict__ bk)
{
    const int b  = blockIdx.y;
    const int l0 = blockIdx.x * 64;

    __shared__ float xs[64][64];
    __shared__ float wqs[64][65];
    __shared__ float wks[64][65];

    const int t  = threadIdx.x;
    const int tx = t & 63;
    const int ty = t >> 6;

    float accq[16], acck[16];
#pragma unroll
    for (int i = 0; i < 16; i++) { accq[i] = 0.f; acck[i] = 0.f; }

    const float* xb = x + (size_t)b * Cc * Ll;
    const int row  = t >> 2;
    const int off0 = (t & 3) * 16;

    for (int cc = 0; cc < Cc; cc += 64) {
#pragma unroll
        for (int j = 0; j < 16; j += 4) {
            float4 v = *(const float4*)(xb + (size_t)(cc + row) * Ll + l0 + off0 + j);
            *(float4*)&xs[row][off0 + j] = v;
        }
#pragma unroll
        for (int j = 0; j < 16; j += 4) {
            float4 vq = *(const float4*)(Wq + row * Cc + cc + off0 + j);
            wqs[off0 + j + 0][row] = vq.x;
            wqs[off0 + j + 1][row] = vq.y;
            wqs[off0 + j + 2][row] = vq.z;
            wqs[off0 + j + 3][row] = vq.w;
            float4 vk = *(const float4*)(Wk + row * Cc + cc + off0 + j);
            wks[off0 + j + 0][row] = vk.x;
            wks[off0 + j + 1][row] = vk.y;
            wks[off0 + j + 2][row] = vk.z;
            wks[off0 + j + 3][row] = vk.w;
        }
        __syncthreads();
#pragma unroll 4
        for (int ci = 0; ci < 64; ci++) {
            float wq = wqs[ci][tx];
            float wk = wks[ci][tx];
#pragma unroll
            for (int i = 0; i < 16; i++) {
                float xv = xs[ci][ty * 16 + i];
                accq[i] = fmaf(wq, xv, accq[i]);
                acck[i] = fmaf(wk, xv, acck[i]);
            }
        }
        __syncthreads();
    }

    const float bqv = bq[tx];
    const float bkv = bk[tx];
#pragma unroll
    for (int i = 0; i < 16; i++) {
        int l = l0 + ty * 16 + i;
        size_t base = ((size_t)b * Ll + l) * Dd;
        g_qa[base + tx] = __float2bfloat16(accq[i] + bqv);
        g_kb[base + tx] = __float2bfloat16(acck[i] + bkv);
    }
}

// ---------------------------------------------------------------------------
__global__ __launch_bounds__(256) void transpose_x_kernel(const float* __restrict__ x)
{
    __shared__ float tile[32][33];
    const int b  = blockIdx.z;
    const int c0 = blockIdx.y * 32;
    const int l0 = blockIdx.x * 32;
    const int tx = threadIdx.x, ty = threadIdx.y;

    const float* xb = x + ((size_t)b * Cc + c0) * Ll + l0;
#pragma unroll
    for (int r = 0; r < 4; r++)
        tile[ty + r * 8][tx] = xb[(size_t)(ty + r * 8) * Ll + tx];
    __syncthreads();

    __nv_bfloat16* o = g_xT + (size_t)b * Ll * Cc;
#pragma unroll
    for (int r = 0; r < 4; r++) {
        int l = l0 + ty + r * 8;
        o[(size_t)l * Cc + c0 + tx] = __float2bfloat16(tile[tx][ty + r * 8]);
    }
}

__global__ __launch_bounds__(256) void conv_wv_kernel(const float* __restrict__ Wv)
{
    int idx = blockIdx.x * 256 + threadIdx.x;
    g_wv[idx] = __float2bfloat16(Wv[idx]);
}

// ---------------------------------------------------------------------------
extern "C" void kernel_launch(void* const* d_in, const int* in_sizes, int n_in,
                              void* d_out, int out_size)
{
    const float* x     = (const float*)d_in[0];
    const float* Wq    = (const float*)d_in[1];
    const float* bq    = (const float*)d_in[2];
    const float* Wk    = (const float*)d_in[3];
    const float* bk    = (const float*)d_in[4];
    const float* Wv    = (const float*)d_in[5];
    const float* bv    = (const float*)d_in[6];
    const float* gamma = (const float*)d_in[7];
    float* out = (float*)d_out;

    __nv_bfloat16 *qa, *kb, *xT, *wv;
    unsigned char *v, *p;
    float *spart, *invs;
    cudaGetSymbolAddress((void**)&qa, g_qa);
    cudaGetSymbolAddress((void**)&kb, g_kb);
    cudaGetSymbolAddress((void**)&xT, g_xT);
    cudaGetSymbolAddress((void**)&wv, g_wv);
    cudaGetSymbolAddress((void**)&v,  g_v);
    cudaGetSymbolAddress((void**)&p,  g_p);
    cudaGetSymbolAddress((void**)&spart, g_spart);
    cudaGetSymbolAddress((void**)&invs,  g_invs);

    cudaFuncSetAttribute(hgemm<1>, cudaFuncAttributeMaxDynamicSharedMemorySize, SMEM_SZ);
    cudaFuncSetAttribute(hgemm<3>, cudaFuncAttributeMaxDynamicSharedMemorySize, SMEM_SZ);
    cudaFuncSetAttribute(fgemm,    cudaFuncAttributeMaxDynamicSharedMemorySize, SMEM_SZ);

    // 1) prologue conversions
    proj_qk_kernel<<<dim3(Ll / 64, Bb), 256>>>(x, Wq, bq, Wk, bk);
    transpose_x_kernel<<<dim3(Ll / 32, Cc / 32, Bb), dim3(32, 8)>>>(x);
    conv_wv_kernel<<<(Cc * Cc) / 256, 256>>>(Wv);

    // 2) v = Wv @ x + bv  -> e4m3 [C, L]
    hgemm<1><<<dim3(Ll / 128, Cc / 128, Bb), 256, SMEM_SZ>>>(
        wv, xT, v, Cc, Ll,
        0LL, (long long)Ll * Cc, (long long)Cc * Ll,
        bv, nullptr);

    // 3) p = exp(q @ k^T)*2^-6  (K=64 bf16) -> e4m3 + row-sum partials
    hgemm<3><<<dim3(Ll / 128, Ll / 128, Bb), 256, SMEM_SZ>>>(
        qa, kb, p, Dd, Ll,
        (long long)Ll * Dd, (long long)Ll * Dd, (long long)Ll * Ll,
        nullptr, spart);

    // 4) invS = 1 / rowsum
    reduce_s_kernel<<<(Bb * Ll) / 256, 256>>>();

    // 5) out = (gamma*invS[i]*64) * (v @ p^T) + x  (fp8 GEMM, K=4096)
    fgemm<<<dim3(Ll / 128, Cc / 128, Bb), 256, SMEM_SZ>>>(
        v, p, out, Ll, Ll,
        (long long)Cc * Ll, (long long)Ll * Ll, (long long)Cc * Ll,
        gamma, x, (long long)Cc * Ll, invs);
}